// round 3
// baseline (speedup 1.0000x reference)
#include <cuda_runtime.h>

#define SLEN 2048
#define NH   16
#define HD   64
#define QT   64
#define KT   64
#define LDP  68          // padded row (floats) for Qs / Vs
#define LDK  132         // padded row (floats) for duplicated Ks2 / Ps2 (33*16B)
#define LOG2E 1.4426950408889634f

typedef unsigned long long u64;

// Scratch (allocation-free rule: __device__ globals)
__device__ float g_KcT[NH * HD * SLEN];   // compacted K, transposed: [h][d][j]
__device__ float g_Vc [NH * SLEN * HD];   // compacted V, row-major:  [h][j][d]
__device__ float g_posf[SLEN];            // (pos - (S-1)) for valid j, -1e30 for pad
__device__ int   g_pos [SLEN];
__device__ int   g_nvalid;

// ---- packed f32x2 helpers (FFMA2: HW-supported, PTX-only on sm_103a) -------
__device__ __forceinline__ void ffma2(u64& acc, u64 a, u64 b) {
    asm("fma.rn.f32x2 %0, %1, %2, %0;" : "+l"(acc) : "l"(a), "l"(b));
}
__device__ __forceinline__ u64 fmul2(u64 a, u64 b) {
    u64 r; asm("mul.rn.f32x2 %0, %1, %2;" : "=l"(r) : "l"(a), "l"(b)); return r;
}
__device__ __forceinline__ u64 pack2(float x, float y) {
    u64 r; asm("mov.b64 %0, {%1, %2};" : "=l"(r) : "f"(x), "f"(y)); return r;
}
__device__ __forceinline__ void unpack2(u64 v, float& lo, float& hi) {
    asm("mov.b64 {%0, %1}, %2;" : "=f"(lo), "=f"(hi) : "l"(v));
}

// ---------------------------------------------------------------------------
// Kernel 1: compact the boolean key mask (layout auto-detect: u8 vs int32).
// ---------------------------------------------------------------------------
__global__ void compact_kernel(const unsigned char* __restrict__ mask8) {
    __shared__ int cnt[256];
    __shared__ int s_n;
    int tid  = threadIdx.x;
    int base = tid * 8;

    int probe = 0;
#pragma unroll
    for (int i = 0; i < 8; i++) {
        int p = base + i;
        if ((p & 3) != 0 && mask8[p] != 0) probe = 1;
    }
    int isU8 = __syncthreads_or(probe);

    const int* mask32 = (const int*)mask8;
    int v[8], c = 0;
#pragma unroll
    for (int i = 0; i < 8; i++) {
        int e = base + i;
        int val = isU8 ? (int)(mask8[e] != 0) : (int)(mask32[e] != 0);
        v[i] = val;
        c += val;
    }
    cnt[tid] = c;
    __syncthreads();
    for (int off = 1; off < 256; off <<= 1) {
        int t = (tid >= off) ? cnt[tid - off] : 0;
        __syncthreads();
        cnt[tid] += t;
        __syncthreads();
    }
    int idx = cnt[tid] - c;
#pragma unroll
    for (int i = 0; i < 8; i++) {
        if (v[i]) {
            g_pos [idx] = base + i;
            g_posf[idx] = (float)(base + i - (SLEN - 1));
            idx++;
        }
    }
    if (tid == 255) { s_n = cnt[255]; g_nvalid = cnt[255]; }
    __syncthreads();
    for (int j = s_n + tid; j < SLEN; j += 256) g_posf[j] = -1.0e30f;
}

// ---------------------------------------------------------------------------
// Kernel 2: gather valid K rows -> [h][d][j] transposed; V -> [h][j][d].
// ---------------------------------------------------------------------------
__global__ void scatter_kernel(const float* __restrict__ K, const float* __restrict__ V) {
    int h   = blockIdx.y;
    int jin = threadIdx.x & 15;
    int d4  = threadIdx.x >> 4;
    int j   = blockIdx.x * 16 + jin;
    int n   = g_nvalid;
    float4 kk = make_float4(0.f, 0.f, 0.f, 0.f);
    float4 vv = kk;
    if (j < n) {
        int src = g_pos[j];
        kk = *(const float4*)(K + ((size_t)h * SLEN + src) * HD + d4 * 4);
        vv = *(const float4*)(V + ((size_t)h * SLEN + src) * HD + d4 * 4);
    }
    float* kt = g_KcT + (size_t)h * HD * SLEN;
    kt[(4 * d4 + 0) * SLEN + j] = kk.x;
    kt[(4 * d4 + 1) * SLEN + j] = kk.y;
    kt[(4 * d4 + 2) * SLEN + j] = kk.z;
    kt[(4 * d4 + 3) * SLEN + j] = kk.w;
    *(float4*)(g_Vc + ((size_t)h * SLEN + j) * HD + d4 * 4) = vv;
}

// ---------------------------------------------------------------------------
// Kernel 3: flash attention, packed-f32x2 math.
//   Qs:  [d][q]  transposed, pre-scaled by (1/8)*log2(e), LDP rows
//   Ks2: [d][2k] value-DUPLICATED pairs {v,v}, LDK rows
//   Vs:  [k][d]  LDP rows
//   Ps2: [q][2k] prob-DUPLICATED pairs {p,p}, LDK rows
// ---------------------------------------------------------------------------
__global__ __launch_bounds__(256) void attn_kernel(const float* __restrict__ Q,
                                                   float* __restrict__ Out) {
    extern __shared__ float sm[];
    float* Qs  = sm;                  // 64*68
    float* Ks2 = Qs  + HD * LDP;      // 64*132
    float* Vs  = Ks2 + HD * LDK;      // 64*68
    float* Ps2 = Vs  + KT * LDP;      // 64*132
    float* djs = Ps2 + QT * LDK;      // 64

    int tid = threadIdx.x;
    int h   = blockIdx.y;
    int q0  = blockIdx.x * QT;
    int ty  = tid >> 4, tx = tid & 15;
    const float scaleL = 0.125f * LOG2E;
    const float slopeL = exp2f(-0.5f * (float)(h + 1)) * LOG2E;  // ALiBi, log2 domain

    // Load Q tile transposed, pre-scaled into the log2 softmax domain
    const float* Qg = Q + ((size_t)h * SLEN + q0) * HD;
#pragma unroll
    for (int idx = tid; idx < QT * 16; idx += 256) {
        int q = idx >> 4, w = idx & 15;
        float4 t = *(const float4*)(Qg + q * HD + w * 4);
        Qs[(4 * w + 0) * LDP + q] = t.x * scaleL;
        Qs[(4 * w + 1) * LDP + q] = t.y * scaleL;
        Qs[(4 * w + 2) * LDP + q] = t.z * scaleL;
        Qs[(4 * w + 3) * LDP + q] = t.w * scaleL;
    }

    u64 o2[4][2];                      // o2[r][h] packs O d-pairs {4tx+2h, 4tx+2h+1}
#pragma unroll
    for (int r = 0; r < 4; r++) { o2[r][0] = 0ull; o2[r][1] = 0ull; }
    float m[4], l[4];
#pragma unroll
    for (int r = 0; r < 4; r++) { m[r] = __int_as_float(0xff800000); l[r] = 0.f; }

    int n      = g_nvalid;
    int ntiles = (n + KT - 1) >> 6;
    const float* KgT = g_KcT + (size_t)h * HD * SLEN;
    const float* Vg  = g_Vc  + (size_t)h * SLEN * HD;

    for (int t = 0; t < ntiles; ++t) {
        int k0 = t * KT;
        __syncthreads();
        // Load K tile DUPLICATED ({v,v} pairs) and V tile.
#pragma unroll
        for (int idx = tid; idx < HD * 16; idx += 256) {
            int row = idx >> 4, c4 = idx & 15;
            float4 kk = *(const float4*)(KgT + row * SLEN + k0 + 4 * c4);
            float* kd = &Ks2[row * LDK + 8 * c4];
            *(float4*)(kd)     = make_float4(kk.x, kk.x, kk.y, kk.y);
            *(float4*)(kd + 4) = make_float4(kk.z, kk.z, kk.w, kk.w);
            float4 vv = *(const float4*)(Vg + (size_t)(k0 + row) * HD + 4 * c4);
            *(float4*)&Vs[row * LDP + 4 * c4] = vv;
        }
        if (tid < KT) djs[tid] = g_posf[k0 + tid];
        __syncthreads();

        // S = Qs . K  (log2 domain), packed along q-row pairs.
        u64 s2[2][4] = {};
#pragma unroll 8
        for (int d = 0; d < HD; ++d) {
            ulonglong2 a2  = *(const ulonglong2*)&Qs [d * LDP + 4 * ty];   // rows {0,1},{2,3}
            ulonglong2 b01 = *(const ulonglong2*)&Ks2[d * LDK + 8 * tx];   // {b0,b0},{b1,b1}
            ulonglong2 b23 = *(const ulonglong2*)&Ks2[d * LDK + 8 * tx + 4];
            ffma2(s2[0][0], a2.x, b01.x); ffma2(s2[1][0], a2.y, b01.x);
            ffma2(s2[0][1], a2.x, b01.y); ffma2(s2[1][1], a2.y, b01.y);
            ffma2(s2[0][2], a2.x, b23.x); ffma2(s2[1][2], a2.y, b23.x);
            ffma2(s2[0][3], a2.x, b23.y); ffma2(s2[1][3], a2.y, b23.y);
        }
        // Unpack, add ALiBi bias (log2 domain).
        float s[4][4];
#pragma unroll
        for (int rp = 0; rp < 2; rp++)
#pragma unroll
            for (int c = 0; c < 4; c++)
                unpack2(s2[rp][c], s[2 * rp][c], s[2 * rp + 1][c]);
        float bj[4];
#pragma unroll
        for (int c = 0; c < 4; c++) bj[c] = slopeL * djs[4 * tx + c];
#pragma unroll
        for (int r = 0; r < 4; r++)
#pragma unroll
            for (int c = 0; c < 4; c++) s[r][c] += bj[c];

        // Online softmax (base-2); rows live within 16-lane tx-groups.
#pragma unroll
        for (int r = 0; r < 4; r++) {
            float tm = fmaxf(fmaxf(s[r][0], s[r][1]), fmaxf(s[r][2], s[r][3]));
            tm = fmaxf(tm, __shfl_xor_sync(0xffffffffu, tm, 8));
            tm = fmaxf(tm, __shfl_xor_sync(0xffffffffu, tm, 4));
            tm = fmaxf(tm, __shfl_xor_sync(0xffffffffu, tm, 2));
            tm = fmaxf(tm, __shfl_xor_sync(0xffffffffu, tm, 1));
            float mn = fmaxf(m[r], tm);
            float al = exp2f(m[r] - mn);
            m[r] = mn;
            s[r][0] = exp2f(s[r][0] - mn);
            s[r][1] = exp2f(s[r][1] - mn);
            s[r][2] = exp2f(s[r][2] - mn);
            s[r][3] = exp2f(s[r][3] - mn);
            float rs = (s[r][0] + s[r][1]) + (s[r][2] + s[r][3]);
            rs += __shfl_xor_sync(0xffffffffu, rs, 8);
            rs += __shfl_xor_sync(0xffffffffu, rs, 4);
            rs += __shfl_xor_sync(0xffffffffu, rs, 2);
            rs += __shfl_xor_sync(0xffffffffu, rs, 1);
            l[r] = l[r] * al + rs;
            u64 alp = pack2(al, al);
            o2[r][0] = fmul2(o2[r][0], alp);
            o2[r][1] = fmul2(o2[r][1], alp);
            // store probs DUPLICATED: {p0,p0,p1,p1},{p2,p2,p3,p3}
            float* pd = &Ps2[(4 * ty + r) * LDK + 8 * tx];
            *(float4*)(pd)     = make_float4(s[r][0], s[r][0], s[r][1], s[r][1]);
            *(float4*)(pd + 4) = make_float4(s[r][2], s[r][2], s[r][3], s[r][3]);
        }
        __syncthreads();

        // O += P V, packed along d-pairs; P pairs {p,p} direct from smem.
#pragma unroll 4
        for (int k4 = 0; k4 < KT / 4; ++k4) {
            ulonglong2 P01[4], P23[4];
#pragma unroll
            for (int r = 0; r < 4; r++) {
                P01[r] = *(const ulonglong2*)&Ps2[(4 * ty + r) * LDK + 8 * k4];
                P23[r] = *(const ulonglong2*)&Ps2[(4 * ty + r) * LDK + 8 * k4 + 4];
            }
#pragma unroll
            for (int i = 0; i < 4; ++i) {
                ulonglong2 v = *(const ulonglong2*)&Vs[(4 * k4 + i) * LDP + 4 * tx];
                u64 pp0 = (i == 0) ? P01[0].x : (i == 1) ? P01[0].y : (i == 2) ? P23[0].x : P23[0].y;
                u64 pp1 = (i == 0) ? P01[1].x : (i == 1) ? P01[1].y : (i == 2) ? P23[1].x : P23[1].y;
                u64 pp2 = (i == 0) ? P01[2].x : (i == 1) ? P01[2].y : (i == 2) ? P23[2].x : P23[2].y;
                u64 pp3 = (i == 0) ? P01[3].x : (i == 1) ? P01[3].y : (i == 2) ? P23[3].x : P23[3].y;
                ffma2(o2[0][0], pp0, v.x); ffma2(o2[0][1], pp0, v.y);
                ffma2(o2[1][0], pp1, v.x); ffma2(o2[1][1], pp1, v.y);
                ffma2(o2[2][0], pp2, v.x); ffma2(o2[2][1], pp2, v.y);
                ffma2(o2[3][0], pp3, v.x); ffma2(o2[3][1], pp3, v.y);
            }
        }
    }

    float* Og = Out + ((size_t)h * SLEN + q0) * HD;
#pragma unroll
    for (int r = 0; r < 4; r++) {
        float inv = 1.0f / l[r];
        float o0, o1, o2f, o3;
        unpack2(o2[r][0], o0, o1);
        unpack2(o2[r][1], o2f, o3);
        *(float4*)(Og + (4 * ty + r) * HD + 4 * tx) =
            make_float4(o0 * inv, o1 * inv, o2f * inv, o3 * inv);
    }
}

// ---------------------------------------------------------------------------
extern "C" void kernel_launch(void* const* d_in, const int* in_sizes, int n_in,
                              void* d_out, int out_size) {
    const float*         Q    = (const float*)d_in[0];
    const float*         K    = (const float*)d_in[1];
    const float*         V    = (const float*)d_in[2];
    const unsigned char* mask = (const unsigned char*)d_in[3];
    float*               out  = (float*)d_out;

    const int SMEM_BYTES = (2 * HD * LDP + 2 * HD * LDK + KT) * (int)sizeof(float); // 102656
    cudaFuncSetAttribute(attn_kernel, cudaFuncAttributeMaxDynamicSharedMemorySize, SMEM_BYTES);

    compact_kernel<<<1, 256>>>(mask);
    dim3 gs(SLEN / 16, NH);
    scatter_kernel<<<gs, 256>>>(K, V);
    dim3 ga(SLEN / QT, NH);
    attn_kernel<<<ga, 256, SMEM_BYTES>>>(Q, out);
}

// round 4
// speedup vs baseline: 3.5189x; 3.5189x over previous
#include <cuda_runtime.h>
#include <cuda_bf16.h>

#define SLEN 2048
#define NH   16
#define HD   64
#define QT   64
#define KT   64
#define STR  72          // bf16 smem row stride: 144B -> ldmatrix conflict-free
#define LOG2E 1.4426950408889634f

// Scratch (allocation-free rule: __device__ globals)
__device__ __nv_bfloat16 g_Kh [NH * SLEN * HD];  // compacted K rows, hi
__device__ __nv_bfloat16 g_Kl [NH * SLEN * HD];  // compacted K rows, lo
__device__ __nv_bfloat16 g_VtH[NH * HD * SLEN];  // compacted V transposed [h][d][j], hi
__device__ __nv_bfloat16 g_VtL[NH * HD * SLEN];  // lo
__device__ float g_posf[SLEN];                   // pos-(S-1) valid, -1e30 pad
__device__ int   g_pos [SLEN];
__device__ int   g_nvalid;

// ---- asm helpers ------------------------------------------------------------
__device__ __forceinline__ void mma_bf16(float (&d)[4], const unsigned (&a)[4],
                                         unsigned b0, unsigned b1) {
    asm("mma.sync.aligned.m16n8k16.row.col.f32.bf16.bf16.f32 "
        "{%0,%1,%2,%3}, {%4,%5,%6,%7}, {%8,%9}, {%0,%1,%2,%3};"
        : "+f"(d[0]), "+f"(d[1]), "+f"(d[2]), "+f"(d[3])
        : "r"(a[0]), "r"(a[1]), "r"(a[2]), "r"(a[3]), "r"(b0), "r"(b1));
}
__device__ __forceinline__ void ldsm4(unsigned (&r)[4], unsigned addr) {
    asm volatile("ldmatrix.sync.aligned.m8n8.x4.shared.b16 {%0,%1,%2,%3}, [%4];"
        : "=r"(r[0]), "=r"(r[1]), "=r"(r[2]), "=r"(r[3]) : "r"(addr));
}
__device__ __forceinline__ void ldsm2(unsigned& r0, unsigned& r1, unsigned addr) {
    asm volatile("ldmatrix.sync.aligned.m8n8.x2.shared.b16 {%0,%1}, [%2];"
        : "=r"(r0), "=r"(r1) : "r"(addr));
}
__device__ __forceinline__ unsigned smem_u32(const void* p) {
    return (unsigned)__cvta_generic_to_shared(p);
}
__device__ __forceinline__ float ex2(float x) {
    float r; asm("ex2.approx.f32 %0, %1;" : "=f"(r) : "f"(x)); return r;
}
// split two fp32 into packed bf16 hi-pair and lo-pair ({x0 low half, x1 high half})
__device__ __forceinline__ void splitpack(float x0, float x1, unsigned& hp, unsigned& lp) {
    __nv_bfloat16 h0 = __float2bfloat16(x0), h1 = __float2bfloat16(x1);
    float r0 = x0 - __bfloat162float(h0), r1 = x1 - __bfloat162float(h1);
    __nv_bfloat16 l0 = __float2bfloat16(r0), l1 = __float2bfloat16(r1);
    hp = ((unsigned)__bfloat16_as_ushort(h1) << 16) | (unsigned)__bfloat16_as_ushort(h0);
    lp = ((unsigned)__bfloat16_as_ushort(l1) << 16) | (unsigned)__bfloat16_as_ushort(l0);
}

// ---------------------------------------------------------------------------
// Kernel 1: mask compaction (layout auto-detect u8 vs int32) — unchanged.
// ---------------------------------------------------------------------------
__global__ void compact_kernel(const unsigned char* __restrict__ mask8) {
    __shared__ int cnt[256];
    __shared__ int s_n;
    int tid  = threadIdx.x;
    int base = tid * 8;
    int probe = 0;
#pragma unroll
    for (int i = 0; i < 8; i++) {
        int p = base + i;
        if ((p & 3) != 0 && mask8[p] != 0) probe = 1;
    }
    int isU8 = __syncthreads_or(probe);
    const int* mask32 = (const int*)mask8;
    int v[8], c = 0;
#pragma unroll
    for (int i = 0; i < 8; i++) {
        int e = base + i;
        int val = isU8 ? (int)(mask8[e] != 0) : (int)(mask32[e] != 0);
        v[i] = val; c += val;
    }
    cnt[tid] = c;
    __syncthreads();
    for (int off = 1; off < 256; off <<= 1) {
        int t = (tid >= off) ? cnt[tid - off] : 0;
        __syncthreads();
        cnt[tid] += t;
        __syncthreads();
    }
    int idx = cnt[tid] - c;
#pragma unroll
    for (int i = 0; i < 8; i++) {
        if (v[i]) {
            g_pos [idx] = base + i;
            g_posf[idx] = (float)(base + i - (SLEN - 1));
            idx++;
        }
    }
    if (tid == 255) { s_n = cnt[255]; g_nvalid = cnt[255]; }
    __syncthreads();
    for (int j = s_n + tid; j < SLEN; j += 256) g_posf[j] = -1.0e30f;
}

// ---------------------------------------------------------------------------
// Kernel 2: gather + fp32->bf16 hi/lo split. K row-major [h][j][d];
// V transposed [h][d][j]. Pads zero-filled.
// ---------------------------------------------------------------------------
__global__ void scatter_kernel(const float* __restrict__ K, const float* __restrict__ V) {
    int h   = blockIdx.y;
    int jin = threadIdx.x & 15;
    int d4  = threadIdx.x >> 4;
    int j   = blockIdx.x * 16 + jin;
    int n   = g_nvalid;
    float4 kk = make_float4(0.f, 0.f, 0.f, 0.f), vv = kk;
    if (j < n) {
        int src = g_pos[j];
        kk = *(const float4*)(K + ((size_t)h * SLEN + src) * HD + d4 * 4);
        vv = *(const float4*)(V + ((size_t)h * SLEN + src) * HD + d4 * 4);
    }
    float ka[4] = {kk.x, kk.y, kk.z, kk.w};
    float va[4] = {vv.x, vv.y, vv.z, vv.w};
    size_t kbase = ((size_t)h * SLEN + j) * HD + 4 * d4;
#pragma unroll
    for (int e = 0; e < 4; e++) {
        __nv_bfloat16 hh = __float2bfloat16(ka[e]);
        __nv_bfloat16 ll = __float2bfloat16(ka[e] - __bfloat162float(hh));
        g_Kh[kbase + e] = hh;
        g_Kl[kbase + e] = ll;
        __nv_bfloat16 vh = __float2bfloat16(va[e]);
        __nv_bfloat16 vl = __float2bfloat16(va[e] - __bfloat162float(vh));
        size_t vt = ((size_t)h * HD + 4 * d4 + e) * SLEN + j;
        g_VtH[vt] = vh;
        g_VtL[vt] = vl;
    }
}

// ---------------------------------------------------------------------------
// Kernel 3: flash attention on tensor cores (bf16 hi/lo 3-term emulation).
// 128 threads = 4 warps; warp w owns q rows 16w..16w+15, full KT=64 per tile.
// ---------------------------------------------------------------------------
__global__ __launch_bounds__(128) void attn_kernel(const float* __restrict__ Q,
                                                   float* __restrict__ Out) {
    extern __shared__ char smem[];
    float* djs = (float*)smem;                                    // 64 floats
    __nv_bfloat16* Qh  = (__nv_bfloat16*)(smem + 256);
    __nv_bfloat16* Ql  = Qh  + QT * STR;
    __nv_bfloat16* KsH = Ql  + QT * STR;
    __nv_bfloat16* KsL = KsH + KT * STR;
    __nv_bfloat16* VtH = KsL + KT * STR;
    __nv_bfloat16* VtL = VtH + HD * STR;

    int tid  = threadIdx.x;
    int w    = tid >> 5, lane = tid & 31;
    int t4   = lane & 3;                        // quad position -> col pairs
    int g    = lane >> 2;                       // row within 8
    int h    = blockIdx.y, q0 = blockIdx.x * QT;
    const float scaleL = 0.125f * LOG2E;
    const float slopeL = exp2f(-0.5f * (float)(h + 1)) * LOG2E;

    // ---- Q tile: load fp32, scale into log2 domain, split hi/lo bf16 ----
    const float* Qg = Q + ((size_t)h * SLEN + q0) * HD;
    for (int idx = tid; idx < QT * 16; idx += 128) {
        int row = idx >> 4, c4 = idx & 15;
        float4 v = *(const float4*)(Qg + row * HD + c4 * 4);
        float a[4] = {v.x * scaleL, v.y * scaleL, v.z * scaleL, v.w * scaleL};
        unsigned hp0, lp0, hp1, lp1;
        splitpack(a[0], a[1], hp0, lp0);
        splitpack(a[2], a[3], hp1, lp1);
        unsigned off = row * STR + 4 * c4;
        *(unsigned*)&Qh[off]     = hp0;
        *(unsigned*)&Qh[off + 2] = hp1;
        *(unsigned*)&Ql[off]     = lp0;
        *(unsigned*)&Ql[off + 2] = lp1;
    }

    // ldmatrix base addresses / lane offsets (bytes)
    unsigned qbH = smem_u32(Qh), qbL = smem_u32(Ql);
    unsigned kbH = smem_u32(KsH), kbL = smem_u32(KsL);
    unsigned vbH = smem_u32(VtH), vbL = smem_u32(VtL);
    // Q x4: row = 16w + (lane&15), col = 16c + 8*(lane>>4)
    unsigned qoff = ((16 * w + (lane & 15)) * STR + 8 * (lane >> 4)) * 2;
    // K/V x2: row = 8*jj + (lane&7), col = 16c + 8*((lane>>3)&1)
    unsigned koff = ((lane & 7) * STR + 8 * ((lane >> 3) & 1)) * 2;

    float oacc[8][4] = {};
    float mM0 = __int_as_float(0xff800000), mM1 = mM0;
    float lS0 = 0.f, lS1 = 0.f;

    int n      = g_nvalid;
    int ntiles = (n + KT - 1) >> 6;

    for (int tt = 0; tt < ntiles; ++tt) {
        int k0 = tt * KT;
        __syncthreads();
        // ---- K/V tile loads (bf16, already split; uint4 = 8 bf16) ----
        {
            const uint4* sKh = (const uint4*)(g_Kh + ((size_t)h * SLEN + k0) * HD);
            const uint4* sKl = (const uint4*)(g_Kl + ((size_t)h * SLEN + k0) * HD);
            for (int idx = tid; idx < 512; idx += 128) {
                int row = idx >> 3, c = idx & 7;
                *(uint4*)&KsH[row * STR + 8 * c] = sKh[idx];
                *(uint4*)&KsL[row * STR + 8 * c] = sKl[idx];
                *(uint4*)&VtH[row * STR + 8 * c] =
                    *(const uint4*)(g_VtH + ((size_t)h * HD + row) * SLEN + k0 + 8 * c);
                *(uint4*)&VtL[row * STR + 8 * c] =
                    *(const uint4*)(g_VtL + ((size_t)h * HD + row) * SLEN + k0 + 8 * c);
            }
            if (tid < KT) djs[tid] = g_posf[k0 + tid];
        }
        __syncthreads();

        // ---- S = Q.K^T (log2 domain), 3-term bf16 emulation ----
        float sacc[8][4];
#pragma unroll
        for (int j = 0; j < 8; j++)
#pragma unroll
            for (int e = 0; e < 4; e++) sacc[j][e] = 0.f;

#pragma unroll
        for (int c = 0; c < 4; c++) {
            unsigned qfh[4], qfl[4];
            ldsm4(qfh, qbH + qoff + 32 * c);
            ldsm4(qfl, qbL + qoff + 32 * c);
            unsigned kh[8][2], kl[8][2];
#pragma unroll
            for (int j = 0; j < 8; j++) {
                unsigned a = koff + j * (8 * STR * 2) + 32 * c;
                ldsm2(kh[j][0], kh[j][1], kbH + a);
                ldsm2(kl[j][0], kl[j][1], kbL + a);
            }
#pragma unroll
            for (int j = 0; j < 8; j++) mma_bf16(sacc[j], qfh, kh[j][0], kh[j][1]);
#pragma unroll
            for (int j = 0; j < 8; j++) mma_bf16(sacc[j], qfh, kl[j][0], kl[j][1]);
#pragma unroll
            for (int j = 0; j < 8; j++) mma_bf16(sacc[j], qfl, kh[j][0], kh[j][1]);
        }

        // ---- ALiBi bias (log2 domain) ----
#pragma unroll
        for (int j = 0; j < 8; j++) {
            float2 b = *(const float2*)&djs[8 * j + 2 * t4];
            sacc[j][0] = fmaf(slopeL, b.x, sacc[j][0]);
            sacc[j][1] = fmaf(slopeL, b.y, sacc[j][1]);
            sacc[j][2] = fmaf(slopeL, b.x, sacc[j][2]);
            sacc[j][3] = fmaf(slopeL, b.y, sacc[j][3]);
        }

        // ---- online softmax (rows r0 = 16w+g, r1 = r0+8; quads share rows) ----
        float tm0 = __int_as_float(0xff800000), tm1 = tm0;
#pragma unroll
        for (int j = 0; j < 8; j++) {
            tm0 = fmaxf(tm0, fmaxf(sacc[j][0], sacc[j][1]));
            tm1 = fmaxf(tm1, fmaxf(sacc[j][2], sacc[j][3]));
        }
        tm0 = fmaxf(tm0, __shfl_xor_sync(0xffffffffu, tm0, 1));
        tm0 = fmaxf(tm0, __shfl_xor_sync(0xffffffffu, tm0, 2));
        tm1 = fmaxf(tm1, __shfl_xor_sync(0xffffffffu, tm1, 1));
        tm1 = fmaxf(tm1, __shfl_xor_sync(0xffffffffu, tm1, 2));
        float mn0 = fmaxf(mM0, tm0), mn1 = fmaxf(mM1, tm1);
        float al0 = ex2(mM0 - mn0), al1 = ex2(mM1 - mn1);
        mM0 = mn0; mM1 = mn1;
        float rs0 = 0.f, rs1 = 0.f;
#pragma unroll
        for (int j = 0; j < 8; j++) {
            sacc[j][0] = ex2(sacc[j][0] - mn0);
            sacc[j][1] = ex2(sacc[j][1] - mn0);
            sacc[j][2] = ex2(sacc[j][2] - mn1);
            sacc[j][3] = ex2(sacc[j][3] - mn1);
            rs0 += sacc[j][0] + sacc[j][1];
            rs1 += sacc[j][2] + sacc[j][3];
        }
        rs0 += __shfl_xor_sync(0xffffffffu, rs0, 1);
        rs0 += __shfl_xor_sync(0xffffffffu, rs0, 2);
        rs1 += __shfl_xor_sync(0xffffffffu, rs1, 1);
        rs1 += __shfl_xor_sync(0xffffffffu, rs1, 2);
        lS0 = lS0 * al0 + rs0;
        lS1 = lS1 * al1 + rs1;
#pragma unroll
        for (int dj = 0; dj < 8; dj++) {
            oacc[dj][0] *= al0; oacc[dj][1] *= al0;
            oacc[dj][2] *= al1; oacc[dj][3] *= al1;
        }

        // ---- O += P.V  (P from S frags: C->A identity, no shuffles) ----
#pragma unroll
        for (int c = 0; c < 4; c++) {
            unsigned ph[4], pl[4];
            splitpack(sacc[2 * c][0],     sacc[2 * c][1],     ph[0], pl[0]);
            splitpack(sacc[2 * c][2],     sacc[2 * c][3],     ph[1], pl[1]);
            splitpack(sacc[2 * c + 1][0], sacc[2 * c + 1][1], ph[2], pl[2]);
            splitpack(sacc[2 * c + 1][2], sacc[2 * c + 1][3], ph[3], pl[3]);
            unsigned vh[8][2], vl[8][2];
#pragma unroll
            for (int dj = 0; dj < 8; dj++) {
                unsigned a = koff + dj * (8 * STR * 2) + 32 * c;
                ldsm2(vh[dj][0], vh[dj][1], vbH + a);
                ldsm2(vl[dj][0], vl[dj][1], vbL + a);
            }
#pragma unroll
            for (int dj = 0; dj < 8; dj++) mma_bf16(oacc[dj], ph, vh[dj][0], vh[dj][1]);
#pragma unroll
            for (int dj = 0; dj < 8; dj++) mma_bf16(oacc[dj], ph, vl[dj][0], vl[dj][1]);
#pragma unroll
            for (int dj = 0; dj < 8; dj++) mma_bf16(oacc[dj], pl, vh[dj][0], vh[dj][1]);
        }
    }

    // ---- normalize & store ----
    float inv0 = 1.0f / lS0, inv1 = 1.0f / lS1;
    int r0 = q0 + 16 * w + g, r1 = r0 + 8;
    float* O0 = Out + ((size_t)h * SLEN + r0) * HD;
    float* O1 = Out + ((size_t)h * SLEN + r1) * HD;
#pragma unroll
    for (int dj = 0; dj < 8; dj++) {
        int col = 8 * dj + 2 * t4;
        *(float2*)&O0[col] = make_float2(oacc[dj][0] * inv0, oacc[dj][1] * inv0);
        *(float2*)&O1[col] = make_float2(oacc[dj][2] * inv1, oacc[dj][3] * inv1);
    }
}

// ---------------------------------------------------------------------------
extern "C" void kernel_launch(void* const* d_in, const int* in_sizes, int n_in,
                              void* d_out, int out_size) {
    const float*         Q    = (const float*)d_in[0];
    const float*         K    = (const float*)d_in[1];
    const float*         V    = (const float*)d_in[2];
    const unsigned char* mask = (const unsigned char*)d_in[3];
    float*               out  = (float*)d_out;

    const int SMEM_BYTES = 256 + 6 * QT * STR * 2;   // 55552
    cudaFuncSetAttribute(attn_kernel, cudaFuncAttributeMaxDynamicSharedMemorySize, SMEM_BYTES);

    compact_kernel<<<1, 256>>>(mask);
    dim3 gs(SLEN / 16, NH);
    scatter_kernel<<<gs, 256>>>(K, V);
    dim3 ga(SLEN / QT, NH);
    attn_kernel<<<ga, 128, SMEM_BYTES>>>(Q, out);
}

// round 5
// speedup vs baseline: 4.1415x; 1.1769x over previous
#include <cuda_runtime.h>
#include <cuda_bf16.h>

#define SLEN 2048
#define NH   16
#define HD   64
#define QT   64
#define KT   64
#define STR  72            // bf16 smem row stride (144B)
#define LOG2E 1.4426950408889634f
#define STAGE_BYTES 37120  // KsH(9216)+KsL(9216)+VtH(9216)+VtL(9216)+djs(256)

// Scratch (allocation-free rule: __device__ globals)
__device__ __nv_bfloat16 g_Kh [NH * SLEN * HD];
__device__ __nv_bfloat16 g_Kl [NH * SLEN * HD];
__device__ __nv_bfloat16 g_VtH[NH * HD * SLEN];   // V transposed [h][d][j]
__device__ __nv_bfloat16 g_VtL[NH * HD * SLEN];
__device__ float g_posf[SLEN];
__device__ int   g_nvalid;

// ---- asm helpers ----------------------------------------------------------
__device__ __forceinline__ void mma_bf16(float (&d)[4], const unsigned (&a)[4],
                                         unsigned b0, unsigned b1) {
    asm("mma.sync.aligned.m16n8k16.row.col.f32.bf16.bf16.f32 "
        "{%0,%1,%2,%3}, {%4,%5,%6,%7}, {%8,%9}, {%0,%1,%2,%3};"
        : "+f"(d[0]), "+f"(d[1]), "+f"(d[2]), "+f"(d[3])
        : "r"(a[0]), "r"(a[1]), "r"(a[2]), "r"(a[3]), "r"(b0), "r"(b1));
}
__device__ __forceinline__ void ldsm4(unsigned (&r)[4], unsigned addr) {
    asm volatile("ldmatrix.sync.aligned.m8n8.x4.shared.b16 {%0,%1,%2,%3}, [%4];"
        : "=r"(r[0]), "=r"(r[1]), "=r"(r[2]), "=r"(r[3]) : "r"(addr));
}
__device__ __forceinline__ unsigned smem_u32(const void* p) {
    return (unsigned)__cvta_generic_to_shared(p);
}
__device__ __forceinline__ float ex2(float x) {
    float r; asm("ex2.approx.f32 %0, %1;" : "=f"(r) : "f"(x)); return r;
}
__device__ __forceinline__ void splitpack(float x0, float x1, unsigned& hp, unsigned& lp) {
    __nv_bfloat16 h0 = __float2bfloat16(x0), h1 = __float2bfloat16(x1);
    float r0 = x0 - __bfloat162float(h0), r1 = x1 - __bfloat162float(h1);
    __nv_bfloat16 l0 = __float2bfloat16(r0), l1 = __float2bfloat16(r1);
    hp = ((unsigned)__bfloat16_as_ushort(h1) << 16) | (unsigned)__bfloat16_as_ushort(h0);
    lp = ((unsigned)__bfloat16_as_ushort(l1) << 16) | (unsigned)__bfloat16_as_ushort(l0);
}
__device__ __forceinline__ void cp16(unsigned dst, const void* src) {
    asm volatile("cp.async.cg.shared.global [%0], [%1], 16;" :: "r"(dst), "l"(src));
}
__device__ __forceinline__ void cp_commit() {
    asm volatile("cp.async.commit_group;");
}
template<int N> __device__ __forceinline__ void cp_wait() {
    asm volatile("cp.async.wait_group %0;" :: "n"(N));
}

// ---------------------------------------------------------------------------
// Kernel 1 (prep): per-CTA redundant mask scan (smem) + gather/split K,V.
// Mask layout auto-detect (u8 vs int32-widened numpy bool).
// ---------------------------------------------------------------------------
__global__ void prep_kernel(const float* __restrict__ K, const float* __restrict__ V,
                            const unsigned char* __restrict__ mask8) {
    __shared__ int   cnt[256];
    __shared__ short s_pos[SLEN];
    __shared__ int   s_n;
    int tid  = threadIdx.x;
    int base = tid * 8;

    int probe = 0;
#pragma unroll
    for (int i = 0; i < 8; i++) {
        int p = base + i;
        if ((p & 3) != 0 && mask8[p] != 0) probe = 1;
    }
    int isU8 = __syncthreads_or(probe);
    const int* mask32 = (const int*)mask8;
    int v[8], c = 0;
#pragma unroll
    for (int i = 0; i < 8; i++) {
        int e = base + i;
        int val = isU8 ? (int)(mask8[e] != 0) : (int)(mask32[e] != 0);
        v[i] = val; c += val;
    }
    cnt[tid] = c;
    __syncthreads();
    for (int off = 1; off < 256; off <<= 1) {
        int t = (tid >= off) ? cnt[tid - off] : 0;
        __syncthreads();
        cnt[tid] += t;
        __syncthreads();
    }
    int idx = cnt[tid] - c;
#pragma unroll
    for (int i = 0; i < 8; i++) {
        if (v[i]) s_pos[idx++] = (short)(base + i);
    }
    if (tid == 255) s_n = cnt[255];
    __syncthreads();
    int n = s_n;

    if (blockIdx.x == 0 && blockIdx.y == 0) {
        for (int j = tid; j < SLEN; j += 256)
            g_posf[j] = (j < n) ? (float)((int)s_pos[j] - (SLEN - 1)) : -1.0e30f;
        if (tid == 0) g_nvalid = n;
    }

    int h   = blockIdx.y;
    int jin = tid & 15;
    int d4  = tid >> 4;
    int j   = blockIdx.x * 16 + jin;
    float4 kk = make_float4(0.f, 0.f, 0.f, 0.f), vv = kk;
    if (j < n) {
        int src = s_pos[j];
        kk = *(const float4*)(K + ((size_t)h * SLEN + src) * HD + d4 * 4);
        vv = *(const float4*)(V + ((size_t)h * SLEN + src) * HD + d4 * 4);
    }
    float ka[4] = {kk.x, kk.y, kk.z, kk.w};
    float va[4] = {vv.x, vv.y, vv.z, vv.w};
    size_t kbase = ((size_t)h * SLEN + j) * HD + 4 * d4;
#pragma unroll
    for (int e = 0; e < 4; e++) {
        __nv_bfloat16 hh = __float2bfloat16(ka[e]);
        __nv_bfloat16 ll = __float2bfloat16(ka[e] - __bfloat162float(hh));
        g_Kh[kbase + e] = hh;
        g_Kl[kbase + e] = ll;
        __nv_bfloat16 vh = __float2bfloat16(va[e]);
        __nv_bfloat16 vl = __float2bfloat16(va[e] - __bfloat162float(vh));
        size_t vt = ((size_t)h * HD + 4 * d4 + e) * SLEN + j;
        g_VtH[vt] = vh;
        g_VtL[vt] = vl;
    }
}

// ---------------------------------------------------------------------------
// prefetch one K/V tile (+djs) into a pipeline stage via cp.async
// ---------------------------------------------------------------------------
__device__ __forceinline__ void prefetch_tile(char* smem, int stage, int h, int k0, int tid) {
    unsigned st = smem_u32(smem + stage * STAGE_BYTES);
    const uint4* gKh = (const uint4*)(g_Kh + ((size_t)h * SLEN + k0) * HD);
    const uint4* gKl = (const uint4*)(g_Kl + ((size_t)h * SLEN + k0) * HD);
#pragma unroll
    for (int i = 0; i < 4; i++) {
        int idx = tid + 128 * i;
        int row = idx >> 3, c = idx & 7;
        unsigned off = (row * STR + 8 * c) * 2;
        cp16(st + off,         gKh + idx);
        cp16(st + 9216 + off,  gKl + idx);
        cp16(st + 18432 + off, (const uint4*)(g_VtH + ((size_t)h * HD + row) * SLEN + k0) + c);
        cp16(st + 27648 + off, (const uint4*)(g_VtL + ((size_t)h * HD + row) * SLEN + k0) + c);
    }
    if (tid < 16) cp16(st + 36864 + tid * 16, (const uint4*)(g_posf + k0) + tid);
}

// ---------------------------------------------------------------------------
// Kernel 2: flash attention, tensor cores, hoisted Q frags, 2-stage cp.async.
// ---------------------------------------------------------------------------
__global__ __launch_bounds__(128, 3) void attn_kernel(const float* __restrict__ Q,
                                                      float* __restrict__ Out) {
    extern __shared__ char smem[];
    int tid  = threadIdx.x;
    int w    = tid >> 5, lane = tid & 31;
    int t4   = lane & 3;
    int g    = lane >> 2;
    int h    = blockIdx.y, q0 = blockIdx.x * QT;
    const float scaleL = 0.125f * LOG2E;
    const float slopeL = exp2f(-0.5f * (float)(h + 1)) * LOG2E;

    int n      = g_nvalid;
    int ntiles = (n + KT - 1) >> 6;

    // stage-0 prefetch first so it flows under the Q prologue
    prefetch_tile(smem, 0, h, 0, tid);
    cp_commit();

    // ---- Q prologue: store scaled+split Q into stage-1 region, ldsm frags ----
    __nv_bfloat16* Qh = (__nv_bfloat16*)(smem + STAGE_BYTES);
    __nv_bfloat16* Ql = Qh + QT * STR;
    const float* Qg = Q + ((size_t)h * SLEN + q0) * HD;
    for (int idx = tid; idx < QT * 16; idx += 128) {
        int row = idx >> 4, c4 = idx & 15;
        float4 v = *(const float4*)(Qg + row * HD + c4 * 4);
        unsigned hp0, lp0, hp1, lp1;
        splitpack(v.x * scaleL, v.y * scaleL, hp0, lp0);
        splitpack(v.z * scaleL, v.w * scaleL, hp1, lp1);
        unsigned off = row * STR + 4 * c4;
        *(unsigned*)&Qh[off]     = hp0;
        *(unsigned*)&Qh[off + 2] = hp1;
        *(unsigned*)&Ql[off]     = lp0;
        *(unsigned*)&Ql[off + 2] = lp1;
    }
    __syncthreads();
    unsigned qbH = smem_u32(Qh), qbL = smem_u32(Ql);
    unsigned qoff = ((16 * w + (lane & 15)) * STR + 8 * (lane >> 4)) * 2;
    unsigned qfh[4][4], qfl[4][4];
#pragma unroll
    for (int c = 0; c < 4; c++) {
        ldsm4(qfh[c], qbH + qoff + 32 * c);
        ldsm4(qfl[c], qbL + qoff + 32 * c);
    }
    __syncthreads();   // Q region free -> stage 1 may be overwritten

    if (ntiles > 1) prefetch_tile(smem, 1, h, KT, tid);
    cp_commit();

    // x4 ldsm lane offset: rows (lane&7) + 8*(lane>>4), col-half (lane>>3)&1
    unsigned koff4 = (((lane & 7) + 8 * (lane >> 4)) * STR + 8 * ((lane >> 3) & 1)) * 2;

    float oacc[8][4] = {};
    float mM0 = __int_as_float(0xff800000), mM1 = mM0;
    float lS0 = 0.f, lS1 = 0.f;

    for (int tt = 0; tt < ntiles; ++tt) {
        char* st = smem + (tt & 1) * STAGE_BYTES;
        unsigned kbH = smem_u32(st), kbL = kbH + 9216;
        unsigned vbH = kbH + 18432, vbL = kbH + 27648;
        const float* djs = (const float*)(st + 36864);

        cp_wait<1>();
        __syncthreads();

        // ---- S = Q.K^T (log2 domain), 3-term bf16 ----
        float sacc[8][4];
#pragma unroll
        for (int j = 0; j < 8; j++)
#pragma unroll
            for (int e = 0; e < 4; e++) sacc[j][e] = 0.f;

#pragma unroll
        for (int c = 0; c < 4; c++) {
            unsigned kh[8][2], kl[8][2];
#pragma unroll
            for (int jp = 0; jp < 4; jp++) {
                unsigned r[4];
                unsigned a = koff4 + (jp * 16 * STR + 16 * c) * 2;
                ldsm4(r, kbH + a);
                kh[2 * jp][0] = r[0]; kh[2 * jp][1] = r[1];
                kh[2 * jp + 1][0] = r[2]; kh[2 * jp + 1][1] = r[3];
                ldsm4(r, kbL + a);
                kl[2 * jp][0] = r[0]; kl[2 * jp][1] = r[1];
                kl[2 * jp + 1][0] = r[2]; kl[2 * jp + 1][1] = r[3];
            }
#pragma unroll
            for (int j = 0; j < 8; j++) mma_bf16(sacc[j], qfh[c], kh[j][0], kh[j][1]);
#pragma unroll
            for (int j = 0; j < 8; j++) mma_bf16(sacc[j], qfh[c], kl[j][0], kl[j][1]);
#pragma unroll
            for (int j = 0; j < 8; j++) mma_bf16(sacc[j], qfl[c], kh[j][0], kh[j][1]);
        }

        // ---- ALiBi bias ----
#pragma unroll
        for (int j = 0; j < 8; j++) {
            float2 b = *(const float2*)&djs[8 * j + 2 * t4];
            sacc[j][0] = fmaf(slopeL, b.x, sacc[j][0]);
            sacc[j][1] = fmaf(slopeL, b.y, sacc[j][1]);
            sacc[j][2] = fmaf(slopeL, b.x, sacc[j][2]);
            sacc[j][3] = fmaf(slopeL, b.y, sacc[j][3]);
        }

        // ---- online softmax ----
        float tm0 = __int_as_float(0xff800000), tm1 = tm0;
#pragma unroll
        for (int j = 0; j < 8; j++) {
            tm0 = fmaxf(tm0, fmaxf(sacc[j][0], sacc[j][1]));
            tm1 = fmaxf(tm1, fmaxf(sacc[j][2], sacc[j][3]));
        }
        tm0 = fmaxf(tm0, __shfl_xor_sync(0xffffffffu, tm0, 1));
        tm0 = fmaxf(tm0, __shfl_xor_sync(0xffffffffu, tm0, 2));
        tm1 = fmaxf(tm1, __shfl_xor_sync(0xffffffffu, tm1, 1));
        tm1 = fmaxf(tm1, __shfl_xor_sync(0xffffffffu, tm1, 2));
        float mn0 = fmaxf(mM0, tm0), mn1 = fmaxf(mM1, tm1);
        float al0 = ex2(mM0 - mn0), al1 = ex2(mM1 - mn1);
        mM0 = mn0; mM1 = mn1;
        float rs0 = 0.f, rs1 = 0.f;
#pragma unroll
        for (int j = 0; j < 8; j++) {
            sacc[j][0] = ex2(sacc[j][0] - mn0);
            sacc[j][1] = ex2(sacc[j][1] - mn0);
            sacc[j][2] = ex2(sacc[j][2] - mn1);
            sacc[j][3] = ex2(sacc[j][3] - mn1);
            rs0 += sacc[j][0] + sacc[j][1];
            rs1 += sacc[j][2] + sacc[j][3];
        }
        rs0 += __shfl_xor_sync(0xffffffffu, rs0, 1);
        rs0 += __shfl_xor_sync(0xffffffffu, rs0, 2);
        rs1 += __shfl_xor_sync(0xffffffffu, rs1, 1);
        rs1 += __shfl_xor_sync(0xffffffffu, rs1, 2);
        lS0 = lS0 * al0 + rs0;
        lS1 = lS1 * al1 + rs1;
#pragma unroll
        for (int dj = 0; dj < 8; dj++) {
            oacc[dj][0] *= al0; oacc[dj][1] *= al0;
            oacc[dj][2] *= al1; oacc[dj][3] *= al1;
        }

        // ---- O += P.V (C->A identity, 3-term bf16) ----
#pragma unroll
        for (int c = 0; c < 4; c++) {
            unsigned ph[4], pl[4];
            splitpack(sacc[2 * c][0],     sacc[2 * c][1],     ph[0], pl[0]);
            splitpack(sacc[2 * c][2],     sacc[2 * c][3],     ph[1], pl[1]);
            splitpack(sacc[2 * c + 1][0], sacc[2 * c + 1][1], ph[2], pl[2]);
            splitpack(sacc[2 * c + 1][2], sacc[2 * c + 1][3], ph[3], pl[3]);
            unsigned vh[8][2], vl[8][2];
#pragma unroll
            for (int jp = 0; jp < 4; jp++) {
                unsigned r[4];
                unsigned a = koff4 + (jp * 16 * STR + 16 * c) * 2;
                ldsm4(r, vbH + a);
                vh[2 * jp][0] = r[0]; vh[2 * jp][1] = r[1];
                vh[2 * jp + 1][0] = r[2]; vh[2 * jp + 1][1] = r[3];
                ldsm4(r, vbL + a);
                vl[2 * jp][0] = r[0]; vl[2 * jp][1] = r[1];
                vl[2 * jp + 1][0] = r[2]; vl[2 * jp + 1][1] = r[3];
            }
#pragma unroll
            for (int dj = 0; dj < 8; dj++) mma_bf16(oacc[dj], ph, vh[dj][0], vh[dj][1]);
#pragma unroll
            for (int dj = 0; dj < 8; dj++) mma_bf16(oacc[dj], ph, vl[dj][0], vl[dj][1]);
#pragma unroll
            for (int dj = 0; dj < 8; dj++) mma_bf16(oacc[dj], pl, vh[dj][0], vh[dj][1]);
        }

        __syncthreads();   // stage fully consumed
        if (tt + 2 < ntiles) prefetch_tile(smem, tt & 1, h, (tt + 2) * KT, tid);
        cp_commit();
    }

    // ---- normalize & store ----
    float inv0 = 1.0f / lS0, inv1 = 1.0f / lS1;
    int r0 = q0 + 16 * w + g, r1 = r0 + 8;
    float* O0 = Out + ((size_t)h * SLEN + r0) * HD;
    float* O1 = Out + ((size_t)h * SLEN + r1) * HD;
#pragma unroll
    for (int dj = 0; dj < 8; dj++) {
        int col = 8 * dj + 2 * t4;
        *(float2*)&O0[col] = make_float2(oacc[dj][0] * inv0, oacc[dj][1] * inv0);
        *(float2*)&O1[col] = make_float2(oacc[dj][2] * inv1, oacc[dj][3] * inv1);
    }
}

// ---------------------------------------------------------------------------
extern "C" void kernel_launch(void* const* d_in, const int* in_sizes, int n_in,
                              void* d_out, int out_size) {
    const float*         Q    = (const float*)d_in[0];
    const float*         K    = (const float*)d_in[1];
    const float*         V    = (const float*)d_in[2];
    const unsigned char* mask = (const unsigned char*)d_in[3];
    float*               out  = (float*)d_out;

    const int SMEM_BYTES = 2 * STAGE_BYTES;   // 74240
    cudaFuncSetAttribute(attn_kernel, cudaFuncAttributeMaxDynamicSharedMemorySize, SMEM_BYTES);

    dim3 gp(SLEN / 16, NH);
    prep_kernel<<<gp, 256>>>(K, V, mask);
    dim3 ga(SLEN / QT, NH);
    attn_kernel<<<ga, 128, SMEM_BYTES>>>(Q, out);
}